// round 1
// baseline (speedup 1.0000x reference)
#include <cuda_runtime.h>

#define E_    8
#define D_    512
#define TMAX  32768

#define TM 128
#define TN 128
#define TK 8

// Scratch (allocation-free: __device__ globals)
__device__ int g_counts[E_];
__device__ int g_offsets[E_];
__device__ int g_cursor[E_];
__device__ int g_bucket[TMAX];

__global__ void k_zero() {
    int i = threadIdx.x;
    if (i < E_) { g_counts[i] = 0; g_cursor[i] = 0; }
}

__global__ void k_count(const int* __restrict__ p, int T) {
    int t = blockIdx.x * blockDim.x + threadIdx.x;
    if (t < T) atomicAdd(&g_counts[p[t]], 1);
}

__global__ void k_prefix() {
    if (threadIdx.x == 0) {
        int acc = 0;
        for (int e = 0; e < E_; e++) { g_offsets[e] = acc; acc += g_counts[e]; }
    }
}

__global__ void k_scatter(const int* __restrict__ p, int T) {
    int t = blockIdx.x * blockDim.x + threadIdx.x;
    if (t < T) {
        int e = p[t];
        int pos = atomicAdd(&g_cursor[e], 1);
        g_bucket[g_offsets[e] + pos] = t;
    }
}

// Grouped SGEMM: out[row] = x[row] @ W[e].T + b[e], rows gathered per expert.
// Block: 256 threads, tile TM=128 x TN=128, K-slab 8, 8x8 microtile/thread.
__global__ __launch_bounds__(256, 2)
void k_gemm(const float* __restrict__ x, const float* __restrict__ W,
            const float* __restrict__ bias, float* __restrict__ out) {
    const int e     = blockIdx.z;
    const int count = g_counts[e];
    const int mtile = blockIdx.y;
    if (mtile * TM >= count) return;          // early-exit empty tiles
    const int ntile = blockIdx.x;
    const int base  = g_offsets[e];

    __shared__ float As[TK][TM];
    __shared__ float Bs[TK][TN];
    __shared__ int   rows[TM];

    const int tid = threadIdx.x;
    if (tid < TM) {
        int m = mtile * TM + tid;
        rows[tid] = (m < count) ? g_bucket[base + m] : -1;
    }
    __syncthreads();

    // Global-load mapping: thread -> (row = tid/2, 4-float chunk = tid%2)
    const int lr = tid >> 1;
    const int lc = (tid & 1) * 4;
    const int arow = rows[lr];
    const float* aptr = (arow >= 0) ? (x + (size_t)arow * D_ + lc) : x + lc; // dummy ptr if pad
    const bool  avalid = (arow >= 0);
    const float* bptr = W + ((size_t)e * D_ + (size_t)(ntile * TN) + lr) * D_ + lc;

    // Compute mapping: 16x16 thread grid, 8x8 microtile
    const int ty = tid >> 4;    // 0..15 -> M rows ty*8..ty*8+7
    const int tx = tid & 15;    // 0..15 -> N cols tx*8..tx*8+7

    float acc[8][8];
    #pragma unroll
    for (int i = 0; i < 8; i++)
        #pragma unroll
        for (int j = 0; j < 8; j++) acc[i][j] = 0.f;

    for (int k0 = 0; k0 < D_; k0 += TK) {
        float4 av = avalid ? *(const float4*)(aptr + k0) : make_float4(0.f, 0.f, 0.f, 0.f);
        float4 bv = *(const float4*)(bptr + k0);
        As[lc + 0][lr] = av.x; As[lc + 1][lr] = av.y;
        As[lc + 2][lr] = av.z; As[lc + 3][lr] = av.w;
        Bs[lc + 0][lr] = bv.x; Bs[lc + 1][lr] = bv.y;
        Bs[lc + 2][lr] = bv.z; Bs[lc + 3][lr] = bv.w;
        __syncthreads();

        #pragma unroll
        for (int k = 0; k < TK; k++) {
            float4 a0 = *(const float4*)&As[k][ty * 8];
            float4 a1 = *(const float4*)&As[k][ty * 8 + 4];
            float4 b0 = *(const float4*)&Bs[k][tx * 8];
            float4 b1 = *(const float4*)&Bs[k][tx * 8 + 4];
            float a[8]  = {a0.x, a0.y, a0.z, a0.w, a1.x, a1.y, a1.z, a1.w};
            float bb[8] = {b0.x, b0.y, b0.z, b0.w, b1.x, b1.y, b1.z, b1.w};
            #pragma unroll
            for (int i = 0; i < 8; i++)
                #pragma unroll
                for (int j = 0; j < 8; j++)
                    acc[i][j] += a[i] * bb[j];
        }
        __syncthreads();
    }

    // Epilogue: add bias, scatter rows back by token id
    const int ncol = ntile * TN + tx * 8;
    float bvals[8];
    #pragma unroll
    for (int j = 0; j < 8; j++) bvals[j] = bias[e * D_ + ncol + j];

    #pragma unroll
    for (int i = 0; i < 8; i++) {
        int r = rows[ty * 8 + i];
        if (r < 0) continue;
        float* orow = out + (size_t)r * D_ + ncol;
        float4 o0 = make_float4(acc[i][0] + bvals[0], acc[i][1] + bvals[1],
                                acc[i][2] + bvals[2], acc[i][3] + bvals[3]);
        float4 o1 = make_float4(acc[i][4] + bvals[4], acc[i][5] + bvals[5],
                                acc[i][6] + bvals[6], acc[i][7] + bvals[7]);
        *(float4*)(orow)     = o0;
        *(float4*)(orow + 4) = o1;
    }
}

extern "C" void kernel_launch(void* const* d_in, const int* in_sizes, int n_in,
                              void* d_out, int out_size) {
    const float* x = (const float*)d_in[0];
    const int*   p = (const int*)d_in[1];
    const float* W = (const float*)d_in[2];
    const float* b = (const float*)d_in[3];
    float* out = (float*)d_out;
    const int T = in_sizes[1];          // 32768 tokens

    k_zero<<<1, 32>>>();
    k_count<<<(T + 255) / 256, 256>>>(p, T);
    k_prefix<<<1, 1>>>();
    k_scatter<<<(T + 255) / 256, 256>>>(p, T);

    dim3 grid(D_ / TN, (T + TM - 1) / TM, E_);
    k_gemm<<<grid, 256>>>(x, W, b, out);
}

// round 3
// speedup vs baseline: 2.4336x; 2.4336x over previous
#include <cuda_runtime.h>
#include <cuda_bf16.h>
#include <cstdint>

#define E_      8
#define D_      512
#define TMAX    32768
#define MAXTILES 264

// ---------------- scratch (allocation-free __device__ globals) ----------------
__device__ int g_counts[E_];
__device__ int g_offsets[E_];
__device__ int g_cursor[E_];
__device__ int g_bucket[TMAX];
__device__ int g_tile_e[MAXTILES];
__device__ int g_tile_m[MAXTILES];
__device__ int g_num_tiles;

__device__ __align__(16) __nv_bfloat16 g_Xhi[(size_t)TMAX * D_];
__device__ __align__(16) __nv_bfloat16 g_Xlo[(size_t)TMAX * D_];
__device__ __align__(16) __nv_bfloat16 g_Whi[(size_t)E_ * D_ * D_];
__device__ __align__(16) __nv_bfloat16 g_Wlo[(size_t)E_ * D_ * D_];

// ---------------- helpers ----------------
__device__ __forceinline__ uint32_t smem_u32(const void* p) {
    uint32_t a;
    asm("{ .reg .u64 t; cvta.to.shared.u64 t, %1; cvt.u32.u64 %0, t; }" : "=r"(a) : "l"(p));
    return a;
}

#define CP16(d, s) asm volatile("cp.async.cg.shared.global [%0], [%1], 16;" :: "r"(d), "l"(s) : "memory")

#define LDSM4(r, a)                                                                  \
    asm volatile("ldmatrix.sync.aligned.m8n8.x4.shared.b16 {%0,%1,%2,%3}, [%4];"     \
        : "=r"((r)[0]), "=r"((r)[1]), "=r"((r)[2]), "=r"((r)[3]) : "r"(a))

#define MMA(c, a, b)                                                                 \
    asm volatile("mma.sync.aligned.m16n8k16.row.col.f32.bf16.bf16.f32 "              \
        "{%0,%1,%2,%3},{%4,%5,%6,%7},{%8,%9},{%0,%1,%2,%3};"                         \
        : "+f"((c)[0]), "+f"((c)[1]), "+f"((c)[2]), "+f"((c)[3])                     \
        : "r"((a)[0]), "r"((a)[1]), "r"((a)[2]), "r"((a)[3]),                        \
          "r"((b)[0]), "r"((b)[1]))

__device__ __forceinline__ void split2(float x, float y,
                                       uint32_t& hi, uint32_t& lo) {
    __nv_bfloat16 hx = __float2bfloat16(x);
    __nv_bfloat16 hy = __float2bfloat16(y);
    __nv_bfloat16 lx = __float2bfloat16(x - __bfloat162float(hx));
    __nv_bfloat16 ly = __float2bfloat16(y - __bfloat162float(hy));
    __nv_bfloat162 h = __halves2bfloat162(hx, hy);
    __nv_bfloat162 l = __halves2bfloat162(lx, ly);
    hi = *(uint32_t*)&h;
    lo = *(uint32_t*)&l;
}

// ---------------- bucketing ----------------
__global__ void k_zero() {
    int i = threadIdx.x;
    if (i < E_) { g_counts[i] = 0; g_cursor[i] = 0; }
}

__global__ void k_count(const int* __restrict__ p, int T) {
    __shared__ int s[E_];
    if (threadIdx.x < E_) s[threadIdx.x] = 0;
    __syncthreads();
    int t = blockIdx.x * blockDim.x + threadIdx.x;
    if (t < T) atomicAdd(&s[p[t]], 1);
    __syncthreads();
    if (threadIdx.x < E_ && s[threadIdx.x]) atomicAdd(&g_counts[threadIdx.x], s[threadIdx.x]);
}

__global__ void k_prefix() {
    if (threadIdx.x == 0) {
        int acc = 0;
        for (int e = 0; e < E_; e++) { g_offsets[e] = acc; acc += g_counts[e]; }
        int nt = 0;
        for (int e = 0; e < E_; e++) {
            int mt = (g_counts[e] + 127) >> 7;
            for (int m = 0; m < mt; m++) { g_tile_e[nt] = e; g_tile_m[nt] = m; nt++; }
        }
        g_num_tiles = nt;
    }
}

__global__ void k_scatter(const int* __restrict__ p, int T) {
    __shared__ int s_cnt[E_], s_base[E_];
    if (threadIdx.x < E_) s_cnt[threadIdx.x] = 0;
    __syncthreads();
    int t = blockIdx.x * blockDim.x + threadIdx.x;
    int e = 0, rank = 0;
    if (t < T) { e = p[t]; rank = atomicAdd(&s_cnt[e], 1); }
    __syncthreads();
    if (threadIdx.x < E_ && s_cnt[threadIdx.x])
        s_base[threadIdx.x] = atomicAdd(&g_cursor[threadIdx.x], s_cnt[threadIdx.x]);
    __syncthreads();
    if (t < T) g_bucket[g_offsets[e] + s_base[e] + rank] = t;
}

// ---------------- fp32 -> bf16 hi/lo pre-split ----------------
__global__ void k_convx(const float* __restrict__ x) {
    int i = blockIdx.x * blockDim.x + threadIdx.x;   // float4 index
    float4 v = ((const float4*)x)[i];
    uint2 h, l;
    split2(v.x, v.y, h.x, l.x);
    split2(v.z, v.w, h.y, l.y);
    ((uint2*)g_Xhi)[i] = h;
    ((uint2*)g_Xlo)[i] = l;
}

__global__ void k_convw(const float* __restrict__ W) {
    int i = blockIdx.x * blockDim.x + threadIdx.x;   // float4 index
    float4 v = ((const float4*)W)[i];
    uint2 h, l;
    split2(v.x, v.y, h.x, l.x);
    split2(v.z, v.w, h.y, l.y);
    ((uint2*)g_Whi)[i] = h;
    ((uint2*)g_Wlo)[i] = l;
}

// ---------------- grouped GEMM: HMMA 3xBF16 split ----------------
// CTA tile 128(M gathered tokens) x 128(N), K=512 in 16 chunks of 32.
// 8 warps, warp tile 32x64. Double-buffered cp.async stages.
// Per stage 4 tiles: Ahi, Alo, Whi, Wlo; each 128 rows x 32 bf16, row stride
// 80 B (16 B pad -> conflict-free ldmatrix).
#define SA          80
#define TILE_BYTES  (128 * SA)        // 10240
#define STAGE_BYTES (4 * TILE_BYTES)  // 40960
#define SMEM_GEMM   (1024 + 2 * STAGE_BYTES)

__global__ void __launch_bounds__(256)
k_gemm(const float* __restrict__ bias, float* __restrict__ out) {
    extern __shared__ unsigned char smem[];
    const int ti = blockIdx.y;
    if (ti >= g_num_tiles) return;
    const int nt    = blockIdx.x;
    const int e     = g_tile_e[ti];
    const int mtile = g_tile_m[ti];
    const int count = g_counts[e];
    const int base  = g_offsets[e];

    int* rows = (int*)smem;
    const int tid = threadIdx.x, lane = tid & 31, wid = tid >> 5;

    if (tid < 128) {
        int m = mtile * 128 + tid;
        rows[tid] = (m < count) ? g_bucket[base + m] : -1;
    }
    __syncthreads();

    // ---- loader setup: thread -> (row = tid/2, 32B chunk pair = tid&1) ----
    const int lrow = tid >> 1;
    const uint32_t lch = (uint32_t)(tid & 1) * 32;   // byte offset within 64B row-window
    int tokA = rows[lrow]; if (tokA < 0) tokA = 0;
    const char* srcAh = (const char*)(g_Xhi + (size_t)tokA * D_) + lch;
    const char* srcAl = (const char*)(g_Xlo + (size_t)tokA * D_) + lch;
    const size_t wrow = ((size_t)e * D_ + (size_t)(nt * 128 + lrow)) * D_;
    const char* srcWh = (const char*)(g_Whi + wrow) + lch;
    const char* srcWl = (const char*)(g_Wlo + wrow) + lch;

    const uint32_t sb = smem_u32(smem) + 1024;
    const uint32_t dsto = (uint32_t)lrow * SA + lch;

    // ---- mma setup ----
    const int m0 = (wid & 3) * 32;
    const int n0 = (wid >> 2) * 64;
    const uint32_t a_off = (uint32_t)(m0 + (lane & 15)) * SA + ((lane >> 4) & 1) * 16;
    uint32_t b_off[4];
    #pragma unroll
    for (int pp = 0; pp < 4; pp++)
        b_off[pp] = (uint32_t)(n0 + pp * 16 + ((lane >> 4) & 1) * 8 + (lane & 7)) * SA
                  + ((lane >> 3) & 1) * 16;

    float acc[2][8][4];
    #pragma unroll
    for (int i = 0; i < 2; i++)
        #pragma unroll
        for (int j = 0; j < 8; j++)
            #pragma unroll
            for (int q = 0; q < 4; q++) acc[i][j][q] = 0.f;

    // ---- pipeline ----
    #define LOAD_STAGE(st, kc) do {                                              \
        uint32_t s_ = sb + (st) * STAGE_BYTES + dsto;                             \
        size_t g_ = (size_t)(kc) * 64;                                           \
        CP16(s_,                  srcAh + g_); CP16(s_ + 16,                  srcAh + g_ + 16); \
        CP16(s_ + TILE_BYTES,     srcAl + g_); CP16(s_ + TILE_BYTES + 16,     srcAl + g_ + 16); \
        CP16(s_ + 2 * TILE_BYTES, srcWh + g_); CP16(s_ + 2 * TILE_BYTES + 16, srcWh + g_ + 16); \
        CP16(s_ + 3 * TILE_BYTES, srcWl + g_); CP16(s_ + 3 * TILE_BYTES + 16, srcWl + g_ + 16); \
        asm volatile("cp.async.commit_group;" ::: "memory");                     \
    } while (0)

    LOAD_STAGE(0, 0);

    for (int kc = 0; kc < 16; kc++) {
        if (kc < 15) {
            LOAD_STAGE((kc + 1) & 1, kc + 1);
            asm volatile("cp.async.wait_group 1;" ::: "memory");
        } else {
            asm volatile("cp.async.wait_group 0;" ::: "memory");
        }
        __syncthreads();

        const uint32_t stb = sb + (kc & 1) * STAGE_BYTES;
        #pragma unroll
        for (int ks = 0; ks < 2; ks++) {
            const uint32_t kso = ks * 32;
            uint32_t ah0[4], ah1[4], al0[4], al1[4];
            LDSM4(ah0, stb + a_off + kso);
            LDSM4(ah1, stb + a_off + 16 * SA + kso);
            LDSM4(al0, stb + TILE_BYTES + a_off + kso);
            LDSM4(al1, stb + TILE_BYTES + a_off + 16 * SA + kso);

            uint32_t bh[8][2], bl[8][2];
            #pragma unroll
            for (int pp = 0; pp < 4; pp++) {
                uint32_t r[4];
                LDSM4(r, stb + 2 * TILE_BYTES + b_off[pp] + kso);
                bh[2 * pp][0] = r[0]; bh[2 * pp][1] = r[1];
                bh[2 * pp + 1][0] = r[2]; bh[2 * pp + 1][1] = r[3];
                LDSM4(r, stb + 3 * TILE_BYTES + b_off[pp] + kso);
                bl[2 * pp][0] = r[0]; bl[2 * pp][1] = r[1];
                bl[2 * pp + 1][0] = r[2]; bl[2 * pp + 1][1] = r[3];
            }

            #pragma unroll
            for (int nb = 0; nb < 8; nb++) {
                MMA(acc[0][nb], ah0, bh[nb]);
                MMA(acc[1][nb], ah1, bh[nb]);
                MMA(acc[0][nb], ah0, bl[nb]);
                MMA(acc[1][nb], ah1, bl[nb]);
                MMA(acc[0][nb], al0, bh[nb]);
                MMA(acc[1][nb], al1, bh[nb]);
            }
        }
        __syncthreads();
    }

    // ---- epilogue: bias + scatter by token ----
    const int gid = lane >> 2, tig = lane & 3;
    const int ncol0 = nt * 128 + n0 + 2 * tig;
    float2 bv[8];
    #pragma unroll
    for (int nb = 0; nb < 8; nb++)
        bv[nb] = *(const float2*)(bias + e * D_ + ncol0 + nb * 8);

    #pragma unroll
    for (int mf = 0; mf < 2; mf++) {
        #pragma unroll
        for (int h = 0; h < 2; h++) {
            int m = m0 + mf * 16 + h * 8 + gid;
            int tok = rows[m];
            if (tok < 0) continue;
            float* orow = out + (size_t)tok * D_ + ncol0;
            #pragma unroll
            for (int nb = 0; nb < 8; nb++) {
                float2 o;
                o.x = acc[mf][nb][2 * h]     + bv[nb].x;
                o.y = acc[mf][nb][2 * h + 1] + bv[nb].y;
                *(float2*)(orow + nb * 8) = o;
            }
        }
    }
}

// ---------------- launch ----------------
extern "C" void kernel_launch(void* const* d_in, const int* in_sizes, int n_in,
                              void* d_out, int out_size) {
    const float* x = (const float*)d_in[0];
    const int*   p = (const int*)d_in[1];
    const float* W = (const float*)d_in[2];
    const float* b = (const float*)d_in[3];
    float* out = (float*)d_out;
    const int T = in_sizes[1];

    static bool attr_done = false;
    if (!attr_done) {
        cudaFuncSetAttribute(k_gemm, cudaFuncAttributeMaxDynamicSharedMemorySize, SMEM_GEMM);
        attr_done = true;
    }

    k_zero<<<1, 32>>>();
    k_count<<<(T + 255) / 256, 256>>>(p, T);
    k_prefix<<<1, 1>>>();
    k_scatter<<<(T + 255) / 256, 256>>>(p, T);
    k_convx<<<(TMAX * D_ / 4) / 256, 256>>>(x);
    k_convw<<<(E_ * D_ * D_ / 4) / 256, 256>>>(W);

    dim3 grid(4, MAXTILES, 1);
    k_gemm<<<grid, 256, SMEM_GEMM>>>(b, out);
}

// round 4
// speedup vs baseline: 2.5845x; 1.0620x over previous
#include <cuda_runtime.h>
#include <cuda_bf16.h>
#include <cstdint>

#define E_      8
#define D_      512
#define TMAX    32768
#define MAXTILES 264

// ---------------- scratch (allocation-free __device__ globals) ----------------
__device__ int g_counts[E_];
__device__ int g_offsets[E_];
__device__ int g_cursor[E_];
__device__ int g_bucket[TMAX];
__device__ int g_tile_e[MAXTILES];
__device__ int g_tile_m[MAXTILES];
__device__ int g_num_tiles;

__device__ __align__(16) __nv_bfloat16 g_Xhi[(size_t)TMAX * D_];
__device__ __align__(16) __nv_bfloat16 g_Xlo[(size_t)TMAX * D_];
__device__ __align__(16) __nv_bfloat16 g_Whi[(size_t)E_ * D_ * D_];
__device__ __align__(16) __nv_bfloat16 g_Wlo[(size_t)E_ * D_ * D_];

// ---------------- helpers ----------------
__device__ __forceinline__ uint32_t smem_u32(const void* p) {
    uint32_t a;
    asm("{ .reg .u64 t; cvta.to.shared.u64 t, %1; cvt.u32.u64 %0, t; }" : "=r"(a) : "l"(p));
    return a;
}

#define CP16(d, s) asm volatile("cp.async.cg.shared.global [%0], [%1], 16;" :: "r"(d), "l"(s) : "memory")

#define LDSM4(r, a)                                                                  \
    asm volatile("ldmatrix.sync.aligned.m8n8.x4.shared.b16 {%0,%1,%2,%3}, [%4];"     \
        : "=r"((r)[0]), "=r"((r)[1]), "=r"((r)[2]), "=r"((r)[3]) : "r"(a))

#define MMA(c, a, b)                                                                 \
    asm volatile("mma.sync.aligned.m16n8k16.row.col.f32.bf16.bf16.f32 "              \
        "{%0,%1,%2,%3},{%4,%5,%6,%7},{%8,%9},{%0,%1,%2,%3};"                         \
        : "+f"((c)[0]), "+f"((c)[1]), "+f"((c)[2]), "+f"((c)[3])                     \
        : "r"((a)[0]), "r"((a)[1]), "r"((a)[2]), "r"((a)[3]),                        \
          "r"((b)[0]), "r"((b)[1]))

__device__ __forceinline__ void split2(float x, float y,
                                       uint32_t& hi, uint32_t& lo) {
    __nv_bfloat16 hx = __float2bfloat16(x);
    __nv_bfloat16 hy = __float2bfloat16(y);
    __nv_bfloat16 lx = __float2bfloat16(x - __bfloat162float(hx));
    __nv_bfloat16 ly = __float2bfloat16(y - __bfloat162float(hy));
    __nv_bfloat162 h = __halves2bfloat162(hx, hy);
    __nv_bfloat162 l = __halves2bfloat162(lx, ly);
    hi = *(uint32_t*)&h;
    lo = *(uint32_t*)&l;
}

// ---------------- bucketing ----------------
__global__ void k_zero() {
    int i = threadIdx.x;
    if (i < E_) { g_counts[i] = 0; g_cursor[i] = 0; }
}

__global__ void k_count(const int* __restrict__ p, int T) {
    __shared__ int s[E_];
    if (threadIdx.x < E_) s[threadIdx.x] = 0;
    __syncthreads();
    int t = blockIdx.x * blockDim.x + threadIdx.x;
    if (t < T) atomicAdd(&s[p[t]], 1);
    __syncthreads();
    if (threadIdx.x < E_ && s[threadIdx.x]) atomicAdd(&g_counts[threadIdx.x], s[threadIdx.x]);
}

__global__ void k_prefix() {
    if (threadIdx.x == 0) {
        int acc = 0;
        for (int e = 0; e < E_; e++) { g_offsets[e] = acc; acc += g_counts[e]; }
        int nt = 0;
        for (int e = 0; e < E_; e++) {
            int mt = (g_counts[e] + 127) >> 7;
            for (int m = 0; m < mt; m++) { g_tile_e[nt] = e; g_tile_m[nt] = m; nt++; }
        }
        g_num_tiles = nt;
    }
}

__global__ void k_scatter(const int* __restrict__ p, int T) {
    __shared__ int s_cnt[E_], s_base[E_];
    if (threadIdx.x < E_) s_cnt[threadIdx.x] = 0;
    __syncthreads();
    int t = blockIdx.x * blockDim.x + threadIdx.x;
    int e = 0, rank = 0;
    if (t < T) { e = p[t]; rank = atomicAdd(&s_cnt[e], 1); }
    __syncthreads();
    if (threadIdx.x < E_ && s_cnt[threadIdx.x])
        s_base[threadIdx.x] = atomicAdd(&g_cursor[threadIdx.x], s_cnt[threadIdx.x]);
    __syncthreads();
    if (t < T) g_bucket[g_offsets[e] + s_base[e] + rank] = t;
}

// ---------------- fp32 -> bf16 hi/lo pre-split ----------------
__global__ void k_convx(const float* __restrict__ x) {
    int i = blockIdx.x * blockDim.x + threadIdx.x;
    float4 v = ((const float4*)x)[i];
    uint2 h, l;
    split2(v.x, v.y, h.x, l.x);
    split2(v.z, v.w, h.y, l.y);
    ((uint2*)g_Xhi)[i] = h;
    ((uint2*)g_Xlo)[i] = l;
}

__global__ void k_convw(const float* __restrict__ W) {
    int i = blockIdx.x * blockDim.x + threadIdx.x;
    float4 v = ((const float4*)W)[i];
    uint2 h, l;
    split2(v.x, v.y, h.x, l.x);
    split2(v.z, v.w, h.y, l.y);
    ((uint2*)g_Whi)[i] = h;
    ((uint2*)g_Wlo)[i] = l;
}

// ---------------- grouped GEMM: HMMA 3xBF16 split, swizzled 3-stage ----------------
// CTA 128(M) x 128(N), K=512 in 16 chunks of 32. 8 warps, warp tile 32x64.
// SMEM tile: 128 rows x 64B, XOR swizzle on 16B chunks: c' = c ^ ((row>>1)&3).
#define TILE_B      8192              // 128 * 64
#define OFF_AH      0
#define OFF_AL      8192
#define OFF_WH      16384
#define OFF_WL      24576
#define STAGE_BYTES 32768
#define NSTAGE      3
#define SMEM_GEMM   (1024 + NSTAGE * STAGE_BYTES)

__global__ void __launch_bounds__(256, 2)
k_gemm(const float* __restrict__ bias, float* __restrict__ out) {
    extern __shared__ unsigned char smem[];
    const int ti = blockIdx.y;
    if (ti >= g_num_tiles) return;
    const int nt    = blockIdx.x;
    const int e     = g_tile_e[ti];
    const int mtile = g_tile_m[ti];
    const int count = g_counts[e];
    const int base  = g_offsets[e];

    int* rows = (int*)smem;
    const int tid = threadIdx.x, lane = tid & 31, wid = tid >> 5;

    if (tid < 128) {
        int m = mtile * 128 + tid;
        rows[tid] = (m < count) ? g_bucket[base + m] : -1;
    }
    __syncthreads();

    // ---- loader setup: thread -> row = tid>>1, 32B half = tid&1 ----
    const int lrow = tid >> 1;
    const uint32_t c0 = (uint32_t)(tid & 1) * 2;           // 16B chunk index 0 or 2
    const uint32_t lsw = (uint32_t)((lrow >> 1) & 3);      // swizzle xor
    const uint32_t d0 = ((c0 ^ lsw) * 16);                 // swizzled chunk byte
    int tokA = rows[lrow]; if (tokA < 0) tokA = 0;
    const char* srcAh = (const char*)(g_Xhi + (size_t)tokA * D_) + c0 * 16;
    const char* srcAl = (const char*)(g_Xlo + (size_t)tokA * D_) + c0 * 16;
    const size_t wrow = ((size_t)e * D_ + (size_t)(nt * 128 + lrow)) * D_;
    const char* srcWh = (const char*)(g_Whi + wrow) + c0 * 16;
    const char* srcWl = (const char*)(g_Wlo + wrow) + c0 * 16;

    const uint32_t sb = smem_u32(smem) + 1024;
    const uint32_t dbase = (uint32_t)lrow * 64;

    // ---- mma fragment addressing ----
    const int m0 = (wid & 3) * 32;
    const int n0 = (wid >> 2) * 64;
    const uint32_t rA  = (uint32_t)(m0 + (lane & 15));
    const uint32_t hA  = (uint32_t)((lane >> 4) & 1);
    const uint32_t sA  = (rA >> 1) & 3;
    const uint32_t rowA = rA * 64;
    const uint32_t rB0 = (uint32_t)(n0 + ((lane >> 4) & 1) * 8 + (lane & 7));
    const uint32_t hB  = (uint32_t)((lane >> 3) & 1);
    const uint32_t sB  = (rB0 >> 1) & 3;
    const uint32_t rowB = rB0 * 64;

    float acc[2][8][4];
    #pragma unroll
    for (int i = 0; i < 2; i++)
        #pragma unroll
        for (int j = 0; j < 8; j++)
            #pragma unroll
            for (int q = 0; q < 4; q++) acc[i][j][q] = 0.f;

    #define LOAD_STAGE(st, kc) do {                                                  \
        uint32_t b_ = sb + (uint32_t)(st) * STAGE_BYTES + dbase + d0;                 \
        size_t g_ = (size_t)(kc) * 64;                                                \
        CP16(b_ + OFF_AH, srcAh + g_); CP16((b_ + OFF_AH) ^ 16, srcAh + g_ + 16);     \
        CP16(b_ + OFF_AL, srcAl + g_); CP16((b_ + OFF_AL) ^ 16, srcAl + g_ + 16);     \
        CP16(b_ + OFF_WH, srcWh + g_); CP16((b_ + OFF_WH) ^ 16, srcWh + g_ + 16);     \
        CP16(b_ + OFF_WL, srcWl + g_); CP16((b_ + OFF_WL) ^ 16, srcWl + g_ + 16);     \
        asm volatile("cp.async.commit_group;" ::: "memory");                          \
    } while (0)

    LOAD_STAGE(0, 0);
    LOAD_STAGE(1, 1);

    int st = 0;      // stage of kc
    int stn = 2;     // stage of kc+2
    for (int kc = 0; kc < 16; kc++) {
        if (kc < 14) {
            asm volatile("cp.async.wait_group 1;" ::: "memory");
        } else {
            asm volatile("cp.async.wait_group 0;" ::: "memory");
        }
        __syncthreads();
        if (kc + 2 < 16) {
            LOAD_STAGE(stn, kc + 2);
            stn = (stn == 2) ? 0 : stn + 1;
        }

        const uint32_t stb = sb + (uint32_t)st * STAGE_BYTES;
        st = (st == 2) ? 0 : st + 1;

        #pragma unroll
        for (int ks = 0; ks < 2; ks++) {
            const uint32_t ca = (((uint32_t)(2 * ks) + hA) ^ sA) * 16;
            const uint32_t cb = (((uint32_t)(2 * ks) + hB) ^ sB) * 16;
            uint32_t ah0[4], ah1[4], al0[4], al1[4];
            LDSM4(ah0, stb + OFF_AH + rowA + ca);
            LDSM4(ah1, stb + OFF_AH + rowA + 1024 + ca);
            LDSM4(al0, stb + OFF_AL + rowA + ca);
            LDSM4(al1, stb + OFF_AL + rowA + 1024 + ca);

            #pragma unroll
            for (int pp = 0; pp < 4; pp++) {
                const uint32_t rb = rowB + (uint32_t)pp * 1024;
                uint32_t bh[4], bl[4];
                LDSM4(bh, stb + OFF_WH + rb + cb);
                LDSM4(bl, stb + OFF_WL + rb + cb);
                // nb = 2*pp : regs {bh[0],bh[1]}; nb = 2*pp+1 : {bh[2],bh[3]}
                MMA(acc[0][2 * pp],     ah0, (bh + 0));
                MMA(acc[1][2 * pp],     ah1, (bh + 0));
                MMA(acc[0][2 * pp + 1], ah0, (bh + 2));
                MMA(acc[1][2 * pp + 1], ah1, (bh + 2));
                MMA(acc[0][2 * pp],     ah0, (bl + 0));
                MMA(acc[1][2 * pp],     ah1, (bl + 0));
                MMA(acc[0][2 * pp + 1], ah0, (bl + 2));
                MMA(acc[1][2 * pp + 1], ah1, (bl + 2));
                MMA(acc[0][2 * pp],     al0, (bh + 0));
                MMA(acc[1][2 * pp],     al1, (bh + 0));
                MMA(acc[0][2 * pp + 1], al0, (bh + 2));
                MMA(acc[1][2 * pp + 1], al1, (bh + 2));
            }
        }
    }

    // ---- epilogue: bias + scatter by token ----
    const int gid = lane >> 2, tig = lane & 3;
    const int ncol0 = nt * 128 + n0 + 2 * tig;
    float2 bv[8];
    #pragma unroll
    for (int nb = 0; nb < 8; nb++)
        bv[nb] = *(const float2*)(bias + e * D_ + ncol0 + nb * 8);

    #pragma unroll
    for (int mf = 0; mf < 2; mf++) {
        #pragma unroll
        for (int h = 0; h < 2; h++) {
            int m = m0 + mf * 16 + h * 8 + gid;
            int tok = rows[m];
            if (tok < 0) continue;
            float* orow = out + (size_t)tok * D_ + ncol0;
            #pragma unroll
            for (int nb = 0; nb < 8; nb++) {
                float2 o;
                o.x = acc[mf][nb][2 * h]     + bv[nb].x;
                o.y = acc[mf][nb][2 * h + 1] + bv[nb].y;
                *(float2*)(orow + nb * 8) = o;
            }
        }
    }
}

// ---------------- launch ----------------
extern "C" void kernel_launch(void* const* d_in, const int* in_sizes, int n_in,
                              void* d_out, int out_size) {
    const float* x = (const float*)d_in[0];
    const int*   p = (const int*)d_in[1];
    const float* W = (const float*)d_in[2];
    const float* b = (const float*)d_in[3];
    float* out = (float*)d_out;
    const int T = in_sizes[1];

    static bool attr_done = false;
    if (!attr_done) {
        cudaFuncSetAttribute(k_gemm, cudaFuncAttributeMaxDynamicSharedMemorySize, SMEM_GEMM);
        attr_done = true;
    }

    k_zero<<<1, 32>>>();
    k_count<<<(T + 255) / 256, 256>>>(p, T);
    k_prefix<<<1, 1>>>();
    k_scatter<<<(T + 255) / 256, 256>>>(p, T);
    k_convx<<<(TMAX * D_ / 4) / 256, 256>>>(x);
    k_convw<<<(E_ * D_ * D_ / 4) / 256, 256>>>(W);

    dim3 grid(4, MAXTILES, 1);
    k_gemm<<<grid, 256, SMEM_GEMM>>>(b, out);
}